// round 1
// baseline (speedup 1.0000x reference)
#include <cuda_runtime.h>
#include <math.h>

// Problem constants
#define BATCH 512
#define TLEN  256
#define IDIM  128
#define HDIM  512

// Tile config
#define BM 64
#define BN 32
#define BK 32
#define NTHREADS 256

// Double-buffered hidden state (device bss; no allocations)
__device__ float g_h[2][BATCH * HDIM];

__device__ __forceinline__ float sigmoidf_(float x) {
    return 1.0f / (1.0f + expf(-x));
}

// One GRU timestep, fused x-projection + h-projection + gates.
// Each CTA: 64 batch rows x 32 hidden columns (all 3 gates for those columns).
__global__ __launch_bounds__(NTHREADS)
void gru_step_kernel(const float* __restrict__ x,
                     const float* __restrict__ W_ih,   // [3H, I]
                     const float* __restrict__ W_hh,   // [3H, H]
                     const float* __restrict__ b_ih,   // [3H]
                     const float* __restrict__ b_hh,   // [3H]
                     int t)
{
    __shared__ float As[BM][BK + 1];
    __shared__ float Ws[3][BK][BN + 1];

    const float* __restrict__ h_in  = g_h[t & 1];
    float* __restrict__       h_out = g_h[(t + 1) & 1];

    const int tid = threadIdx.x;
    const int b0 = blockIdx.y * BM;
    const int j0 = blockIdx.x * BN;

    const int tx = tid & 15;    // 16 col groups
    const int ty = tid >> 4;    // 16 row groups
    const int c0 = tx * 2;      // 2 cols / thread
    const int r0 = ty * 4;      // 4 rows / thread

    float acc_r[4][2]  = {};    // combined x+h reset gate preact
    float acc_z[4][2]  = {};    // combined x+h update gate preact
    float acc_xn[4][2] = {};    // x-side of n gate
    float acc_hn[4][2] = {};    // h-side of n gate (gets multiplied by r)

    // ---------------- Phase 1: x_t @ W_ih^T  (K = IDIM) ----------------
    const float* xt = x + (size_t)t * IDIM;   // x[b*T*I + t*I + i]
    for (int k0 = 0; k0 < IDIM; k0 += BK) {
        // Load A tile (x rows), coalesced along k
        #pragma unroll
        for (int i = tid; i < BM * BK; i += NTHREADS) {
            int row = i >> 5, kk = i & 31;
            As[row][kk] = xt[(size_t)(b0 + row) * (TLEN * IDIM) + (k0 + kk)];
        }
        // Load W tiles for 3 gates, transposed into [g][k][c], coalesced along k
        #pragma unroll
        for (int i = tid; i < 3 * BN * BK; i += NTHREADS) {
            int kk = i & 31;
            int gc = i >> 5;            // g*BN + c
            int g  = gc >> 5;           // /BN
            int c  = gc & 31;
            Ws[g][kk][c] = W_ih[(size_t)(g * HDIM + j0 + c) * IDIM + (k0 + kk)];
        }
        __syncthreads();

        #pragma unroll
        for (int kk = 0; kk < BK; kk++) {
            float a[4];
            #pragma unroll
            for (int i = 0; i < 4; i++) a[i] = As[r0 + i][kk];
            float wr0 = Ws[0][kk][c0], wr1 = Ws[0][kk][c0 + 1];
            float wz0 = Ws[1][kk][c0], wz1 = Ws[1][kk][c0 + 1];
            float wn0 = Ws[2][kk][c0], wn1 = Ws[2][kk][c0 + 1];
            #pragma unroll
            for (int i = 0; i < 4; i++) {
                acc_r[i][0]  = fmaf(a[i], wr0, acc_r[i][0]);
                acc_r[i][1]  = fmaf(a[i], wr1, acc_r[i][1]);
                acc_z[i][0]  = fmaf(a[i], wz0, acc_z[i][0]);
                acc_z[i][1]  = fmaf(a[i], wz1, acc_z[i][1]);
                acc_xn[i][0] = fmaf(a[i], wn0, acc_xn[i][0]);
                acc_xn[i][1] = fmaf(a[i], wn1, acc_xn[i][1]);
            }
        }
        __syncthreads();
    }

    // ---------------- Phase 2: h @ W_hh^T  (K = HDIM) ----------------
    for (int k0 = 0; k0 < HDIM; k0 += BK) {
        #pragma unroll
        for (int i = tid; i < BM * BK; i += NTHREADS) {
            int row = i >> 5, kk = i & 31;
            As[row][kk] = h_in[(size_t)(b0 + row) * HDIM + (k0 + kk)];
        }
        #pragma unroll
        for (int i = tid; i < 3 * BN * BK; i += NTHREADS) {
            int kk = i & 31;
            int gc = i >> 5;
            int g  = gc >> 5;
            int c  = gc & 31;
            Ws[g][kk][c] = W_hh[(size_t)(g * HDIM + j0 + c) * HDIM + (k0 + kk)];
        }
        __syncthreads();

        #pragma unroll
        for (int kk = 0; kk < BK; kk++) {
            float a[4];
            #pragma unroll
            for (int i = 0; i < 4; i++) a[i] = As[r0 + i][kk];
            float wr0 = Ws[0][kk][c0], wr1 = Ws[0][kk][c0 + 1];
            float wz0 = Ws[1][kk][c0], wz1 = Ws[1][kk][c0 + 1];
            float wn0 = Ws[2][kk][c0], wn1 = Ws[2][kk][c0 + 1];
            #pragma unroll
            for (int i = 0; i < 4; i++) {
                acc_r[i][0]  = fmaf(a[i], wr0, acc_r[i][0]);
                acc_r[i][1]  = fmaf(a[i], wr1, acc_r[i][1]);
                acc_z[i][0]  = fmaf(a[i], wz0, acc_z[i][0]);
                acc_z[i][1]  = fmaf(a[i], wz1, acc_z[i][1]);
                acc_hn[i][0] = fmaf(a[i], wn0, acc_hn[i][0]);
                acc_hn[i][1] = fmaf(a[i], wn1, acc_hn[i][1]);
            }
        }
        __syncthreads();
    }

    // ---------------- Epilogue: gates + state update ----------------
    #pragma unroll
    for (int cc = 0; cc < 2; cc++) {
        int j = j0 + c0 + cc;
        float br = b_ih[j]            + b_hh[j];
        float bz = b_ih[HDIM + j]     + b_hh[HDIM + j];
        float bxn = b_ih[2 * HDIM + j];
        float bhn = b_hh[2 * HDIM + j];
        #pragma unroll
        for (int i = 0; i < 4; i++) {
            int b = b0 + r0 + i;
            float r = sigmoidf_(acc_r[i][cc] + br);
            float z = sigmoidf_(acc_z[i][cc] + bz);
            float n = tanhf(acc_xn[i][cc] + bxn + r * (acc_hn[i][cc] + bhn));
            float hprev = h_in[(size_t)b * HDIM + j];
            h_out[(size_t)b * HDIM + j] = (1.0f - z) * n + z * hprev;
        }
    }
}

__global__ void zero_h_kernel()
{
    int i = blockIdx.x * blockDim.x + threadIdx.x;
    if (i < BATCH * HDIM) g_h[0][i] = 0.0f;
}

// out[b] = h_T[b] . W_lin + b_lin   — one warp per batch row
__global__ void final_linear_kernel(const float* __restrict__ W_lin,
                                    const float* __restrict__ b_lin,
                                    float* __restrict__ out)
{
    const float* __restrict__ hT = g_h[TLEN & 1];   // buffer holding h after step T-1
    int warp = (blockIdx.x * blockDim.x + threadIdx.x) >> 5;
    int lane = threadIdx.x & 31;
    if (warp >= BATCH) return;
    float s = 0.0f;
    #pragma unroll
    for (int k = lane; k < HDIM; k += 32)
        s += hT[(size_t)warp * HDIM + k] * W_lin[k];
    #pragma unroll
    for (int off = 16; off; off >>= 1)
        s += __shfl_down_sync(0xFFFFFFFFu, s, off);
    if (lane == 0) out[warp] = s + b_lin[0];
}

extern "C" void kernel_launch(void* const* d_in, const int* in_sizes, int n_in,
                              void* d_out, int out_size)
{
    (void)in_sizes; (void)n_in; (void)out_size;
    const float* x     = (const float*)d_in[0];   // [B, T, I]
    const float* W_ih  = (const float*)d_in[1];   // [3H, I]
    const float* W_hh  = (const float*)d_in[2];   // [3H, H]
    const float* b_ih  = (const float*)d_in[3];   // [3H]
    const float* b_hh  = (const float*)d_in[4];   // [3H]
    const float* W_lin = (const float*)d_in[5];   // [1, H]
    const float* b_lin = (const float*)d_in[6];   // [1]
    float* out = (float*)d_out;                   // [B, 1]

    zero_h_kernel<<<(BATCH * HDIM + 255) / 256, 256>>>();

    dim3 grid(HDIM / BN, BATCH / BM);   // 16 x 8 = 128 CTAs
    for (int t = 0; t < TLEN; t++) {
        gru_step_kernel<<<grid, NTHREADS>>>(x, W_ih, W_hh, b_ih, b_hh, t);
    }

    final_linear_kernel<<<(BATCH * 32 + 255) / 256, 256>>>(W_lin, b_lin, out);
}

// round 4
// speedup vs baseline: 1.6968x; 1.6968x over previous
#include <cuda_runtime.h>
#include <cuda_bf16.h>
#include <cstdint>
#include <math.h>

#define BATCH 512
#define TLEN  256
#define IDIM  128
#define HDIM  512
#define NPACK 1536        // 16 blocks * (r|z|nh) * 32
#define MTILE 64
#define NTILE 96
#define NTH   128

// ---------------- device globals (static; no allocations) ----------------
__device__ __align__(128) float          g_Hf[2][BATCH * HDIM];
__device__ __align__(128) __nv_bfloat16  g_Hhi[2][BATCH * HDIM];
__device__ __align__(128) __nv_bfloat16  g_Hlo[2][BATCH * HDIM];
__device__ __align__(128) __nv_bfloat16  g_Xhi[(size_t)BATCH * TLEN * IDIM];
__device__ __align__(128) __nv_bfloat16  g_Xlo[(size_t)BATCH * TLEN * IDIM];
__device__ __align__(128) __nv_bfloat16  g_Whh_hi[NPACK * HDIM];
__device__ __align__(128) __nv_bfloat16  g_Whh_lo[NPACK * HDIM];
__device__ __align__(128) __nv_bfloat16  g_Wih_hi[NPACK * IDIM];
__device__ __align__(128) __nv_bfloat16  g_Wih_lo[NPACK * IDIM];
__device__ __align__(128) float          g_XG[(size_t)TLEN * BATCH * NPACK]; // [t][b][n]

// ---------------- asm helpers (all plain sm_80/90 PTX; no 'a' features) --
__device__ __forceinline__ uint32_t smem_u32(const void* p) {
    uint32_t a;
    asm("{ .reg .u64 t; cvta.to.shared.u64 t, %1; cvt.u32.u64 %0, t; }"
        : "=r"(a) : "l"(p));
    return a;
}
__device__ __forceinline__ void cp16(uint32_t s, const void* g) {
    asm volatile("cp.async.cg.shared.global [%0], [%1], 16;" :: "r"(s), "l"(g));
}
__device__ __forceinline__ void cp_commit() {
    asm volatile("cp.async.commit_group;" ::: "memory");
}
template<int N> __device__ __forceinline__ void cp_wait() {
    asm volatile("cp.async.wait_group %0;" :: "n"(N) : "memory");
}
__device__ __forceinline__ void ldsm_x4(uint32_t& r0, uint32_t& r1,
                                        uint32_t& r2, uint32_t& r3, uint32_t a) {
    asm volatile("ldmatrix.sync.aligned.m8n8.x4.shared.b16 {%0,%1,%2,%3}, [%4];"
        : "=r"(r0), "=r"(r1), "=r"(r2), "=r"(r3) : "r"(a));
}
__device__ __forceinline__ void mma16816(float* d,
        uint32_t a0, uint32_t a1, uint32_t a2, uint32_t a3,
        uint32_t b0, uint32_t b1) {
    asm volatile(
        "mma.sync.aligned.m16n8k16.row.col.f32.bf16.bf16.f32 "
        "{%0,%1,%2,%3}, {%4,%5,%6,%7}, {%8,%9}, {%0,%1,%2,%3};"
        : "+f"(d[0]), "+f"(d[1]), "+f"(d[2]), "+f"(d[3])
        : "r"(a0), "r"(a1), "r"(a2), "r"(a3), "r"(b0), "r"(b1));
}
__device__ __forceinline__ float sigmoidf_(float x) {
    return 1.0f / (1.0f + expf(-x));
}

// smem tile: rows of 64 bf16 (128B), 16B chunks xor-swizzled by (row&7)
__device__ __forceinline__ uint32_t tile_addr(uint32_t base, int row, int chunk) {
    return base + row * 128 + ((chunk ^ (row & 7)) << 4);
}

// Load one 64x64 A tile + 96x64 B tile (bf16) via cp.async
__device__ __forceinline__ void load_tile(uint32_t sA, uint32_t sB,
        const __nv_bfloat16* __restrict__ gA, int ldA,
        const __nv_bfloat16* __restrict__ gB, int ldB, int tid)
{
    #pragma unroll
    for (int it = 0; it < 4; it++) {                 // A: 512 16B chunks
        int v = tid + it * NTH;
        int r = v >> 3, c = v & 7;
        cp16(tile_addr(sA, r, c), gA + (size_t)r * ldA + c * 8);
    }
    #pragma unroll
    for (int it = 0; it < 6; it++) {                 // B: 768 16B chunks
        int v = tid + it * NTH;
        int r = v >> 3, c = v & 7;
        cp16(tile_addr(sB, r, c), gB + (size_t)r * ldB + c * 8);
    }
}

// 64 K over one buffered tile pair: warp tile 32x48
__device__ __forceinline__ void mma_chunk(uint32_t sA, uint32_t sB,
        int lane, int wm, int wn, float acc[2][6][4])
{
    #pragma unroll
    for (int ks = 0; ks < 4; ks++) {
        uint32_t a[2][4];
        #pragma unroll
        for (int mt = 0; mt < 2; mt++) {
            int row = wm + mt * 16 + (lane & 15);
            int ch  = ks * 2 + (lane >> 4);
            ldsm_x4(a[mt][0], a[mt][1], a[mt][2], a[mt][3],
                    tile_addr(sA, row, ch));
        }
        uint32_t bq[3][4];
        #pragma unroll
        for (int bt = 0; bt < 3; bt++) {
            int row = wn + bt * 16 + (lane & 15);
            int ch  = ks * 2 + (lane >> 4);
            ldsm_x4(bq[bt][0], bq[bt][1], bq[bt][2], bq[bt][3],
                    tile_addr(sB, row, ch));
        }
        #pragma unroll
        for (int mt = 0; mt < 2; mt++)
            #pragma unroll
            for (int nb = 0; nb < 6; nb++) {
                int bt = nb >> 1, h = nb & 1;
                mma16816(acc[mt][nb],
                         a[mt][0], a[mt][1], a[mt][2], a[mt][3],
                         bq[bt][h ? 1 : 0], bq[bt][h ? 3 : 2]);
            }
    }
}

// ---------------- setup kernels ----------------
__global__ void pack_whh_kernel(const float* __restrict__ W_hh)
{
    int idx = blockIdx.x * blockDim.x + threadIdx.x;
    if (idx >= NPACK * HDIM) return;
    int n = idx / HDIM, k = idx - n * HDIM;
    int jb = n / 96, rem = n - jb * 96;
    int g = rem >> 5, jj = rem & 31;
    int row = g * HDIM + jb * 32 + jj;
    float w = W_hh[(size_t)row * HDIM + k];
    __nv_bfloat16 hi = __float2bfloat16(w);
    g_Whh_hi[idx] = hi;
    g_Whh_lo[idx] = __float2bfloat16(w - __bfloat162float(hi));
}

__global__ void pack_wih_kernel(const float* __restrict__ W_ih)
{
    int idx = blockIdx.x * blockDim.x + threadIdx.x;
    if (idx >= NPACK * IDIM) return;
    int n = idx / IDIM, k = idx - n * IDIM;
    int jb = n / 96, rem = n - jb * 96;
    int g = rem >> 5, jj = rem & 31;
    int row = g * HDIM + jb * 32 + jj;
    float w = W_ih[(size_t)row * IDIM + k];
    __nv_bfloat16 hi = __float2bfloat16(w);
    g_Wih_hi[idx] = hi;
    g_Wih_lo[idx] = __float2bfloat16(w - __bfloat162float(hi));
}

__global__ void convert_x_kernel(const float* __restrict__ x)
{
    size_t idx = (size_t)blockIdx.x * blockDim.x + threadIdx.x;
    if (idx >= (size_t)BATCH * TLEN * IDIM) return;
    float v = x[idx];
    __nv_bfloat16 hi = __float2bfloat16(v);
    g_Xhi[idx] = hi;
    g_Xlo[idx] = __float2bfloat16(v - __bfloat162float(hi));
}

__global__ void init_h_kernel()
{
    int idx = blockIdx.x * blockDim.x + threadIdx.x;
    if (idx < BATCH * HDIM) {
        g_Hf[0][idx]  = 0.0f;
        g_Hhi[0][idx] = __float2bfloat16(0.0f);
        g_Hlo[0][idx] = __float2bfloat16(0.0f);
    }
}

// ---------------- xg = x @ W_ih^T (packed cols), 3-term split ----------------
__global__ __launch_bounds__(NTH, 1)
void xg_gemm_kernel()
{
    __shared__ __align__(128) char smem[40960];
    const int tid = threadIdx.x, lane = tid & 31, wid = tid >> 5;
    const int n0 = blockIdx.x * NTILE;
    const int m0 = blockIdx.y * MTILE;       // over B*T = 131072 rows
    const int wm = (wid & 1) * 32, wn = (wid >> 1) * 48;
    uint32_t sbase = smem_u32(smem);

    const __nv_bfloat16* Asrc[3] = {
        g_Xhi + (size_t)m0 * IDIM, g_Xlo + (size_t)m0 * IDIM,
        g_Xhi + (size_t)m0 * IDIM };
    const __nv_bfloat16* Bsrc[3] = {
        g_Wih_hi + (size_t)n0 * IDIM, g_Wih_hi + (size_t)n0 * IDIM,
        g_Wih_lo + (size_t)n0 * IDIM };

    float acc[2][6][4] = {};
    const int NC = 6;                         // 3 terms x 2 chunks of 64
    auto issue = [&](int ci) {
        int term = ci >> 1, kb = (ci & 1) * 64;
        uint32_t b = (uint32_t)(ci & 1) * 20480;
        load_tile(sbase + b, sbase + b + 8192,
                  Asrc[term] + kb, IDIM, Bsrc[term] + kb, IDIM, tid);
        cp_commit();
    };
    issue(0);
    for (int ci = 0; ci < NC; ci++) {
        if (ci + 1 < NC) { issue(ci + 1); cp_wait<1>(); }
        else             { cp_wait<0>(); }
        __syncthreads();
        uint32_t b = (uint32_t)(ci & 1) * 20480;
        mma_chunk(sbase + b, sbase + b + 8192, lane, wm, wn, acc);
        __syncthreads();
    }

    // stage to smem, then coalesced packed write
    float* sC = (float*)smem;                // 64 x 100
    #pragma unroll
    for (int mt = 0; mt < 2; mt++)
        #pragma unroll
        for (int nb = 0; nb < 6; nb++) {
            int row = wm + mt * 16 + (lane >> 2);
            int col = wn + nb * 8 + (lane & 3) * 2;
            sC[row * 100 + col]           = acc[mt][nb][0];
            sC[row * 100 + col + 1]       = acc[mt][nb][1];
            sC[(row + 8) * 100 + col]     = acc[mt][nb][2];
            sC[(row + 8) * 100 + col + 1] = acc[mt][nb][3];
        }
    __syncthreads();
    for (int e = tid; e < MTILE * NTILE; e += NTH) {
        int row = e / NTILE, c = e - row * NTILE;
        int rg = m0 + row;
        int b = rg >> 8, t = rg & 255;       // x rows are (b, t): rg = b*256 + t
        g_XG[((size_t)t * BATCH + b) * NPACK + n0 + c] = sC[row * 100 + c];
    }
}

// ---------------- per-step: h @ W_hh^T (packed) + gates ----------------
__global__ __launch_bounds__(NTH, 1)
void gru_step_kernel(const float* __restrict__ b_ih,
                     const float* __restrict__ b_hh, int t)
{
    __shared__ __align__(128) char smem[40960];
    __shared__ float sb[4][32];
    const int tid = threadIdx.x, lane = tid & 31, wid = tid >> 5;
    const int jb = blockIdx.x;               // 0..15
    const int m0 = blockIdx.y * MTILE;       // 0..448
    const int n0 = jb * NTILE;
    const int hin = t & 1, hout = hin ^ 1;
    const int wm = (wid & 1) * 32, wn = (wid >> 1) * 48;
    uint32_t sbase = smem_u32(smem);

    if (tid < 32) {
        int j = jb * 32 + tid;
        sb[0][tid] = b_ih[j] + b_hh[j];
        sb[1][tid] = b_ih[HDIM + j] + b_hh[HDIM + j];
        sb[2][tid] = b_hh[2 * HDIM + j];
        sb[3][tid] = b_ih[2 * HDIM + j];
    }

    const __nv_bfloat16* Asrc[3] = {
        g_Hhi[hin] + (size_t)m0 * HDIM, g_Hlo[hin] + (size_t)m0 * HDIM,
        g_Hhi[hin] + (size_t)m0 * HDIM };
    const __nv_bfloat16* Bsrc[3] = {
        g_Whh_hi + (size_t)n0 * HDIM, g_Whh_hi + (size_t)n0 * HDIM,
        g_Whh_lo + (size_t)n0 * HDIM };

    float acc[2][6][4] = {};
    const int NC = 24;                       // 3 terms x 8 chunks of 64
    auto issue = [&](int ci) {
        int term = ci >> 3, kb = (ci & 7) * 64;
        uint32_t b = (uint32_t)(ci & 1) * 20480;
        load_tile(sbase + b, sbase + b + 8192,
                  Asrc[term] + kb, HDIM, Bsrc[term] + kb, HDIM, tid);
        cp_commit();
    };
    issue(0);
    for (int ci = 0; ci < NC; ci++) {
        if (ci + 1 < NC) { issue(ci + 1); cp_wait<1>(); }
        else             { cp_wait<0>(); }
        __syncthreads();
        uint32_t b = (uint32_t)(ci & 1) * 20480;
        mma_chunk(sbase + b, sbase + b + 8192, lane, wm, wn, acc);
        __syncthreads();
    }

    // stage C to smem (h-side preacts): cols [0,32)=r  [32,64)=z  [64,96)=nh
    float* sC = (float*)smem;                // 64 x 100
    #pragma unroll
    for (int mt = 0; mt < 2; mt++)
        #pragma unroll
        for (int nb = 0; nb < 6; nb++) {
            int row = wm + mt * 16 + (lane >> 2);
            int col = wn + nb * 8 + (lane & 3) * 2;
            sC[row * 100 + col]           = acc[mt][nb][0];
            sC[row * 100 + col + 1]       = acc[mt][nb][1];
            sC[(row + 8) * 100 + col]     = acc[mt][nb][2];
            sC[(row + 8) * 100 + col + 1] = acc[mt][nb][3];
        }
    __syncthreads();

    const float* __restrict__ xg =
        g_XG + ((size_t)t * BATCH + m0) * NPACK + n0;
    for (int e = tid; e < MTILE * 32; e += NTH) {
        int row = e >> 5, jj = e & 31;
        const float* xr = xg + (size_t)row * NPACK;
        float pr = sC[row * 100 + jj]      + xr[jj]      + sb[0][jj];
        float pz = sC[row * 100 + 32 + jj] + xr[32 + jj] + sb[1][jj];
        float hn = sC[row * 100 + 64 + jj] + sb[2][jj];
        float xn = xr[64 + jj] + sb[3][jj];
        float r = sigmoidf_(pr);
        float z = sigmoidf_(pz);
        float n = tanhf(xn + r * hn);
        size_t gi = (size_t)(m0 + row) * HDIM + jb * 32 + jj;
        float hp = g_Hf[hin][gi];
        float hv = (1.0f - z) * n + z * hp;
        g_Hf[hout][gi] = hv;
        __nv_bfloat16 hi = __float2bfloat16(hv);
        g_Hhi[hout][gi] = hi;
        g_Hlo[hout][gi] = __float2bfloat16(hv - __bfloat162float(hi));
    }
}

// ---------------- final linear ----------------
__global__ void final_linear_kernel(const float* __restrict__ W_lin,
                                    const float* __restrict__ b_lin,
                                    float* __restrict__ out)
{
    const float* __restrict__ hT = g_Hf[0];  // T=256 even -> buffer 0
    int warp = (blockIdx.x * blockDim.x + threadIdx.x) >> 5;
    int lane = threadIdx.x & 31;
    if (warp >= BATCH) return;
    float s = 0.0f;
    #pragma unroll
    for (int k = lane; k < HDIM; k += 32)
        s += hT[(size_t)warp * HDIM + k] * W_lin[k];
    #pragma unroll
    for (int off = 16; off; off >>= 1)
        s += __shfl_down_sync(0xFFFFFFFFu, s, off);
    if (lane == 0) out[warp] = s + b_lin[0];
}

// ---------------- launch ----------------
extern "C" void kernel_launch(void* const* d_in, const int* in_sizes, int n_in,
                              void* d_out, int out_size)
{
    (void)in_sizes; (void)n_in; (void)out_size;
    const float* x     = (const float*)d_in[0];
    const float* W_ih  = (const float*)d_in[1];
    const float* W_hh  = (const float*)d_in[2];
    const float* b_ih  = (const float*)d_in[3];
    const float* b_hh  = (const float*)d_in[4];
    const float* W_lin = (const float*)d_in[5];
    const float* b_lin = (const float*)d_in[6];
    float* out = (float*)d_out;

    pack_whh_kernel<<<(NPACK * HDIM + 255) / 256, 256>>>(W_hh);
    pack_wih_kernel<<<(NPACK * IDIM + 255) / 256, 256>>>(W_ih);
    {
        size_t n = (size_t)BATCH * TLEN * IDIM;
        convert_x_kernel<<<(unsigned)((n + 255) / 256), 256>>>(x);
    }
    init_h_kernel<<<(BATCH * HDIM + 255) / 256, 256>>>();

    // xg over all (b,t): grid (16 nblocks, 131072/64 mtiles)
    xg_gemm_kernel<<<dim3(16, (BATCH * TLEN) / MTILE), NTH>>>();

    dim3 sgrid(16, BATCH / MTILE);           // 16 x 8 = 128 CTAs
    for (int t = 0; t < TLEN; t++) {
        gru_step_kernel<<<sgrid, NTH>>>(b_ih, b_hh, t);
    }

    final_linear_kernel<<<(BATCH * 32 + 255) / 256, 256>>>(W_lin, b_lin, out);
}

// round 5
// speedup vs baseline: 2.0507x; 1.2086x over previous
#include <cuda_runtime.h>
#include <cuda_bf16.h>
#include <cstdint>
#include <math.h>

#define BATCH 512
#define TLEN  256
#define IDIM  128
#define HDIM  512
#define NPACK 1536        // 16 blocks * (r|z|nh) * 32
#define MTILE 64
#define NTILE 96
#define NTH   128

// ---- dynamic smem layout for persistent kernel (bytes) ----
#define SM_WHI   0          // 8 tiles x 12288 = 98304  (W_hh hi, resident)
#define SM_WLO   98304      // 2 x 12288 = 24576        (W_hh lo, streamed)
#define SM_AHI   122880     // 2 x 8192  = 16384        (h hi)
#define SM_ALO   139264     // 2 x 8192  = 16384        (h lo)
#define SM_HPREV 155648     // 64*32*4   = 8192         (fp32 h slice, persists)
#define SM_C     163840     // 64*100*4  = 25600        (epilogue staging)
#define DSMEM    189440

// ---------------- device globals (static; no allocations) ----------------
__device__ __align__(128) float          g_Hf[BATCH * HDIM];        // final h only
__device__ __align__(128) __nv_bfloat16  g_Hhi[2][BATCH * HDIM];
__device__ __align__(128) __nv_bfloat16  g_Hlo[2][BATCH * HDIM];
__device__ __align__(128) __nv_bfloat16  g_Xhi[(size_t)BATCH * TLEN * IDIM];
__device__ __align__(128) __nv_bfloat16  g_Xlo[(size_t)BATCH * TLEN * IDIM];
__device__ __align__(128) __nv_bfloat16  g_Whh_hi[NPACK * HDIM];
__device__ __align__(128) __nv_bfloat16  g_Whh_lo[NPACK * HDIM];
__device__ __align__(128) __nv_bfloat16  g_Wih_hi[NPACK * IDIM];
__device__ __align__(128) __nv_bfloat16  g_Wih_lo[NPACK * IDIM];
__device__ __align__(128) float          g_XG[(size_t)TLEN * BATCH * NPACK]; // [t][b][n]
__device__ unsigned g_bar[8];

// ---------------- asm helpers (plain sm_80/90 PTX) ----------------
__device__ __forceinline__ uint32_t smem_u32(const void* p) {
    uint32_t a;
    asm("{ .reg .u64 t; cvta.to.shared.u64 t, %1; cvt.u32.u64 %0, t; }"
        : "=r"(a) : "l"(p));
    return a;
}
__device__ __forceinline__ void cp16(uint32_t s, const void* g) {
    asm volatile("cp.async.cg.shared.global [%0], [%1], 16;" :: "r"(s), "l"(g));
}
__device__ __forceinline__ void cp_commit() {
    asm volatile("cp.async.commit_group;" ::: "memory");
}
template<int N> __device__ __forceinline__ void cp_wait() {
    asm volatile("cp.async.wait_group %0;" :: "n"(N) : "memory");
}
__device__ __forceinline__ void ldsm_x4(uint32_t& r0, uint32_t& r1,
                                        uint32_t& r2, uint32_t& r3, uint32_t a) {
    asm volatile("ldmatrix.sync.aligned.m8n8.x4.shared.b16 {%0,%1,%2,%3}, [%4];"
        : "=r"(r0), "=r"(r1), "=r"(r2), "=r"(r3) : "r"(a));
}
__device__ __forceinline__ void mma16816(float* d,
        uint32_t a0, uint32_t a1, uint32_t a2, uint32_t a3,
        uint32_t b0, uint32_t b1) {
    asm volatile(
        "mma.sync.aligned.m16n8k16.row.col.f32.bf16.bf16.f32 "
        "{%0,%1,%2,%3}, {%4,%5,%6,%7}, {%8,%9}, {%0,%1,%2,%3};"
        : "+f"(d[0]), "+f"(d[1]), "+f"(d[2]), "+f"(d[3])
        : "r"(a0), "r"(a1), "r"(a2), "r"(a3), "r"(b0), "r"(b1));
}
__device__ __forceinline__ float sigmoidf_(float x) {
    return 1.0f / (1.0f + expf(-x));
}
// smem tile: rows of 64 bf16 (128B), 16B chunks xor-swizzled by (row&7)
__device__ __forceinline__ uint32_t tile_addr(uint32_t base, int row, int chunk) {
    return base + row * 128 + ((chunk ^ (row & 7)) << 4);
}

// ---------------- setup kernels ----------------
__global__ void pack_whh_kernel(const float* __restrict__ W_hh)
{
    int idx = blockIdx.x * blockDim.x + threadIdx.x;
    if (idx >= NPACK * HDIM) return;
    int n = idx / HDIM, k = idx - n * HDIM;
    int jb = n / 96, rem = n - jb * 96;
    int g = rem >> 5, jj = rem & 31;
    int row = g * HDIM + jb * 32 + jj;
    float w = W_hh[(size_t)row * HDIM + k];
    __nv_bfloat16 hi = __float2bfloat16(w);
    g_Whh_hi[idx] = hi;
    g_Whh_lo[idx] = __float2bfloat16(w - __bfloat162float(hi));
}

__global__ void pack_wih_kernel(const float* __restrict__ W_ih)
{
    int idx = blockIdx.x * blockDim.x + threadIdx.x;
    if (idx >= NPACK * IDIM) return;
    int n = idx / IDIM, k = idx - n * IDIM;
    int jb = n / 96, rem = n - jb * 96;
    int g = rem >> 5, jj = rem & 31;
    int row = g * HDIM + jb * 32 + jj;
    float w = W_ih[(size_t)row * IDIM + k];
    __nv_bfloat16 hi = __float2bfloat16(w);
    g_Wih_hi[idx] = hi;
    g_Wih_lo[idx] = __float2bfloat16(w - __bfloat162float(hi));
}

__global__ void convert_x_kernel(const float* __restrict__ x)
{
    size_t idx = (size_t)blockIdx.x * blockDim.x + threadIdx.x;
    if (idx >= (size_t)BATCH * TLEN * IDIM) return;
    float v = x[idx];
    __nv_bfloat16 hi = __float2bfloat16(v);
    g_Xhi[idx] = hi;
    g_Xlo[idx] = __float2bfloat16(v - __bfloat162float(hi));
}

__global__ void init_h_kernel()
{
    int idx = blockIdx.x * blockDim.x + threadIdx.x;
    if (idx < BATCH * HDIM) {
        g_Hhi[0][idx] = __float2bfloat16(0.0f);
        g_Hlo[0][idx] = __float2bfloat16(0.0f);
    }
    if (idx < 8) g_bar[idx] = 0u;
}

// ---------------- xg = x @ W_ih^T (packed cols), 3-term split ----------------
__global__ __launch_bounds__(NTH, 1)
void xg_gemm_kernel()
{
    __shared__ __align__(128) char smem[40960];
    const int tid = threadIdx.x, lane = tid & 31, wid = tid >> 5;
    const int n0 = blockIdx.x * NTILE;
    const int m0 = blockIdx.y * MTILE;       // over B*T = 131072 rows
    const int wm = (wid & 1) * 32, wn = (wid >> 1) * 48;
    uint32_t sbase = smem_u32(smem);

    const __nv_bfloat16* Asrc[3] = {
        g_Xhi + (size_t)m0 * IDIM, g_Xlo + (size_t)m0 * IDIM,
        g_Xhi + (size_t)m0 * IDIM };
    const __nv_bfloat16* Bsrc[3] = {
        g_Wih_hi + (size_t)n0 * IDIM, g_Wih_hi + (size_t)n0 * IDIM,
        g_Wih_lo + (size_t)n0 * IDIM };

    float acc[2][6][4] = {};
    const int NC = 6;                        // 3 terms x 2 chunks of 64
    auto issue = [&](int ci) {
        int term = ci >> 1, kb = (ci & 1) * 64;
        uint32_t b = (uint32_t)(ci & 1) * 20480;
        const __nv_bfloat16* gA = Asrc[term] + kb;
        const __nv_bfloat16* gB = Bsrc[term] + kb;
        #pragma unroll
        for (int it = 0; it < 4; it++) {
            int v = tid + it * NTH; int r = v >> 3, c = v & 7;
            cp16(tile_addr(sbase + b, r, c), gA + (size_t)r * IDIM + c * 8);
        }
        #pragma unroll
        for (int it = 0; it < 6; it++) {
            int v = tid + it * NTH; int r = v >> 3, c = v & 7;
            cp16(tile_addr(sbase + b + 8192, r, c), gB + (size_t)r * IDIM + c * 8);
        }
        cp_commit();
    };
    issue(0);
    for (int ci = 0; ci < NC; ci++) {
        if (ci + 1 < NC) { issue(ci + 1); cp_wait<1>(); }
        else             { cp_wait<0>(); }
        __syncthreads();
        uint32_t sA = sbase + (uint32_t)(ci & 1) * 20480;
        uint32_t sB = sA + 8192;
        #pragma unroll
        for (int ks = 0; ks < 4; ks++) {
            uint32_t a[2][4];
            #pragma unroll
            for (int mt = 0; mt < 2; mt++)
                ldsm_x4(a[mt][0], a[mt][1], a[mt][2], a[mt][3],
                        tile_addr(sA, wm + mt * 16 + (lane & 15), ks * 2 + (lane >> 4)));
            uint32_t bq[3][4];
            #pragma unroll
            for (int bt = 0; bt < 3; bt++)
                ldsm_x4(bq[bt][0], bq[bt][1], bq[bt][2], bq[bt][3],
                        tile_addr(sB, wn + bt * 16 + (lane & 15), ks * 2 + (lane >> 4)));
            #pragma unroll
            for (int mt = 0; mt < 2; mt++)
                #pragma unroll
                for (int nb = 0; nb < 6; nb++) {
                    int bt = nb >> 1, h = nb & 1;
                    mma16816(acc[mt][nb], a[mt][0], a[mt][1], a[mt][2], a[mt][3],
                             bq[bt][h ? 1 : 0], bq[bt][h ? 3 : 2]);
                }
        }
        __syncthreads();
    }

    float* sC = (float*)smem;                // 64 x 100
    #pragma unroll
    for (int mt = 0; mt < 2; mt++)
        #pragma unroll
        for (int nb = 0; nb < 6; nb++) {
            int row = wm + mt * 16 + (lane >> 2);
            int col = wn + nb * 8 + (lane & 3) * 2;
            sC[row * 100 + col]           = acc[mt][nb][0];
            sC[row * 100 + col + 1]       = acc[mt][nb][1];
            sC[(row + 8) * 100 + col]     = acc[mt][nb][2];
            sC[(row + 8) * 100 + col + 1] = acc[mt][nb][3];
        }
    __syncthreads();
    for (int e = tid; e < MTILE * NTILE; e += NTH) {
        int row = e / NTILE, c = e - row * NTILE;
        int rg = m0 + row;
        int b = rg >> 8, t = rg & 255;       // x rows are (b, t)
        g_XG[((size_t)t * BATCH + b) * NPACK + n0 + c] = sC[row * 100 + c];
    }
}

// ---------------- persistent scan kernel ----------------
// grid (16, 8): jb = blockIdx.x (96 packed cols), mt = blockIdx.y (64 batch rows).
// All 128 CTAs co-resident (1/SM). W_hh hi resident in smem; per m-tile group
// barrier (16 CTAs) between steps; h double-buffered by step parity.
__global__ __launch_bounds__(NTH, 1)
void gru_scan_kernel(const float* __restrict__ b_ih,
                     const float* __restrict__ b_hh)
{
    extern __shared__ __align__(128) char smem[];
    __shared__ float sb[4][32];

    const int tid = threadIdx.x, lane = tid & 31, wid = tid >> 5;
    const int jb = blockIdx.x;               // 0..15
    const int mt = blockIdx.y;               // 0..7
    const int m0 = mt * MTILE;
    const int n0 = jb * NTILE;
    const int wm = (wid & 1) * 32, wn = (wid >> 1) * 48;
    uint32_t sbase = smem_u32(smem);
    float* sHprev = (float*)(smem + SM_HPREV);   // [64][32]
    float* sC     = (float*)(smem + SM_C);       // [64][100]

    // ---- preamble: W_hh hi resident (8 tiles of 96x64), bias, h slice ----
    for (int v = tid; v < 8 * 768; v += NTH) {   // 768 16B chunks per tile
        int kc = v / 768, rem = v - kc * 768;
        int r = rem >> 3, c = rem & 7;
        cp16(tile_addr(sbase + SM_WHI + kc * 12288, r, c),
             g_Whh_hi + (size_t)(n0 + r) * HDIM + kc * 64 + c * 8);
    }
    cp_commit();
    if (tid < 32) {
        int j = jb * 32 + tid;
        sb[0][tid] = b_ih[j] + b_hh[j];
        sb[1][tid] = b_ih[HDIM + j] + b_hh[HDIM + j];
        sb[2][tid] = b_hh[2 * HDIM + j];
        sb[3][tid] = b_ih[2 * HDIM + j];
    }
    for (int e = tid; e < MTILE * 32; e += NTH) sHprev[e] = 0.0f;
    cp_wait<0>();
    __syncthreads();

    volatile unsigned* bar = (volatile unsigned*)&g_bar[mt];

    for (int t = 0; t < TLEN; t++) {
        // ---- group barrier: wait for all 16 CTAs of this m-tile ----
        if (t) {
            if (tid == 0) {
                unsigned target = 16u * (unsigned)t;
                while (*bar < target) { }
                __threadfence();
            }
            __syncthreads();
        }

        const __nv_bfloat16* __restrict__ hh = g_Hhi[t & 1];
        const __nv_bfloat16* __restrict__ hl = g_Hlo[t & 1];

        float acc[2][6][4] = {};

        auto issue = [&](int kc) {
            int buf = kc & 1;
            int kb = kc * 64;
            uint32_t aHi = sbase + SM_AHI + (uint32_t)buf * 8192;
            uint32_t aLo = sbase + SM_ALO + (uint32_t)buf * 8192;
            uint32_t wLo = sbase + SM_WLO + (uint32_t)buf * 12288;
            #pragma unroll
            for (int it = 0; it < 4; it++) {
                int v = tid + it * NTH; int r = v >> 3, c = v & 7;
                cp16(tile_addr(aHi, r, c), hh + (size_t)(m0 + r) * HDIM + kb + c * 8);
            }
            #pragma unroll
            for (int it = 0; it < 4; it++) {
                int v = tid + it * NTH; int r = v >> 3, c = v & 7;
                cp16(tile_addr(aLo, r, c), hl + (size_t)(m0 + r) * HDIM + kb + c * 8);
            }
            #pragma unroll
            for (int it = 0; it < 6; it++) {
                int v = tid + it * NTH; int r = v >> 3, c = v & 7;
                cp16(tile_addr(wLo, r, c),
                     g_Whh_lo + (size_t)(n0 + r) * HDIM + kb + c * 8);
            }
            cp_commit();
        };

        issue(0);
        for (int kc = 0; kc < 8; kc++) {
            if (kc < 7) { issue(kc + 1); cp_wait<1>(); }
            else        { cp_wait<0>(); }
            __syncthreads();
            int buf = kc & 1;
            uint32_t aHi = sbase + SM_AHI + (uint32_t)buf * 8192;
            uint32_t aLo = sbase + SM_ALO + (uint32_t)buf * 8192;
            uint32_t bHi = sbase + SM_WHI + (uint32_t)kc * 12288;
            uint32_t bLo = sbase + SM_WLO + (uint32_t)buf * 12288;
            #pragma unroll
            for (int ks = 0; ks < 4; ks++) {
                int ch = ks * 2 + (lane >> 4);
                uint32_t ah[2][4], al[2][4], bh[3][4], bl[3][4];
                #pragma unroll
                for (int mi = 0; mi < 2; mi++) {
                    int row = wm + mi * 16 + (lane & 15);
                    ldsm_x4(ah[mi][0], ah[mi][1], ah[mi][2], ah[mi][3],
                            tile_addr(aHi, row, ch));
                    ldsm_x4(al[mi][0], al[mi][1], al[mi][2], al[mi][3],
                            tile_addr(aLo, row, ch));
                }
                #pragma unroll
                for (int bt = 0; bt < 3; bt++) {
                    int row = wn + bt * 16 + (lane & 15);
                    ldsm_x4(bh[bt][0], bh[bt][1], bh[bt][2], bh[bt][3],
                            tile_addr(bHi, row, ch));
                    ldsm_x4(bl[bt][0], bl[bt][1], bl[bt][2], bl[bt][3],
                            tile_addr(bLo, row, ch));
                }
                // term 0: h_hi * W_hi
                #pragma unroll
                for (int mi = 0; mi < 2; mi++)
                    #pragma unroll
                    for (int nb = 0; nb < 6; nb++) {
                        int bt = nb >> 1, h = nb & 1;
                        mma16816(acc[mi][nb], ah[mi][0], ah[mi][1], ah[mi][2], ah[mi][3],
                                 bh[bt][h ? 1 : 0], bh[bt][h ? 3 : 2]);
                    }
                // term 1: h_lo * W_hi
                #pragma unroll
                for (int mi = 0; mi < 2; mi++)
                    #pragma unroll
                    for (int nb = 0; nb < 6; nb++) {
                        int bt = nb >> 1, h = nb & 1;
                        mma16816(acc[mi][nb], al[mi][0], al[mi][1], al[mi][2], al[mi][3],
                                 bh[bt][h ? 1 : 0], bh[bt][h ? 3 : 2]);
                    }
                // term 2: h_hi * W_lo
                #pragma unroll
                for (int mi = 0; mi < 2; mi++)
                    #pragma unroll
                    for (int nb = 0; nb < 6; nb++) {
                        int bt = nb >> 1, h = nb & 1;
                        mma16816(acc[mi][nb], ah[mi][0], ah[mi][1], ah[mi][2], ah[mi][3],
                                 bl[bt][h ? 1 : 0], bl[bt][h ? 3 : 2]);
                    }
            }
            __syncthreads();
        }

        // ---- epilogue: stage h-preacts, combine with xg, update h ----
        #pragma unroll
        for (int mi = 0; mi < 2; mi++)
            #pragma unroll
            for (int nb = 0; nb < 6; nb++) {
                int row = wm + mi * 16 + (lane >> 2);
                int col = wn + nb * 8 + (lane & 3) * 2;
                sC[row * 100 + col]           = acc[mi][nb][0];
                sC[row * 100 + col + 1]       = acc[mi][nb][1];
                sC[(row + 8) * 100 + col]     = acc[mi][nb][2];
                sC[(row + 8) * 100 + col + 1] = acc[mi][nb][3];
            }
        __syncthreads();

        {
            const int hout = (t + 1) & 1;
            const float* __restrict__ xg =
                g_XG + ((size_t)t * BATCH + m0) * NPACK + n0;
            for (int e = tid; e < MTILE * 32; e += NTH) {
                int row = e >> 5, jj = e & 31;
                const float* xr = xg + (size_t)row * NPACK;
                float pr = sC[row * 100 + jj]      + xr[jj]      + sb[0][jj];
                float pz = sC[row * 100 + 32 + jj] + xr[32 + jj] + sb[1][jj];
                float hn = sC[row * 100 + 64 + jj] + sb[2][jj];
                float xn = xr[64 + jj] + sb[3][jj];
                float r = sigmoidf_(pr);
                float z = sigmoidf_(pz);
                float n = tanhf(xn + r * hn);
                float hp = sHprev[e];
                float hv = (1.0f - z) * n + z * hp;
                sHprev[e] = hv;
                size_t gi = (size_t)(m0 + row) * HDIM + jb * 32 + jj;
                if (t + 1 < TLEN) {
                    __nv_bfloat16 hi = __float2bfloat16(hv);
                    g_Hhi[hout][gi] = hi;
                    g_Hlo[hout][gi] = __float2bfloat16(hv - __bfloat162float(hi));
                } else {
                    g_Hf[gi] = hv;
                }
            }
        }

        // ---- arrive ----
        if (t + 1 < TLEN) {
            __threadfence();
            __syncthreads();
            if (tid == 0) atomicAdd(&g_bar[mt], 1u);
        }
    }
}

// ---------------- final linear ----------------
__global__ void final_linear_kernel(const float* __restrict__ W_lin,
                                    const float* __restrict__ b_lin,
                                    float* __restrict__ out)
{
    const float* __restrict__ hT = g_Hf;
    int warp = (blockIdx.x * blockDim.x + threadIdx.x) >> 5;
    int lane = threadIdx.x & 31;
    if (warp >= BATCH) return;
    float s = 0.0f;
    #pragma unroll
    for (int k = lane; k < HDIM; k += 32)
        s += hT[(size_t)warp * HDIM + k] * W_lin[k];
    #pragma unroll
    for (int off = 16; off; off >>= 1)
        s += __shfl_down_sync(0xFFFFFFFFu, s, off);
    if (lane == 0) out[warp] = s + b_lin[0];
}

// ---------------- launch ----------------
extern "C" void kernel_launch(void* const* d_in, const int* in_sizes, int n_in,
                              void* d_out, int out_size)
{
    (void)in_sizes; (void)n_in; (void)out_size;
    const float* x     = (const float*)d_in[0];
    const float* W_ih  = (const float*)d_in[1];
    const float* W_hh  = (const float*)d_in[2];
    const float* b_ih  = (const float*)d_in[3];
    const float* b_hh  = (const float*)d_in[4];
    const float* W_lin = (const float*)d_in[5];
    const float* b_lin = (const float*)d_in[6];
    float* out = (float*)d_out;

    static int configured = 0;
    if (!configured) {
        cudaFuncSetAttribute(gru_scan_kernel,
                             cudaFuncAttributeMaxDynamicSharedMemorySize, DSMEM);
        configured = 1;
    }

    pack_whh_kernel<<<(NPACK * HDIM + 255) / 256, 256>>>(W_hh);
    pack_wih_kernel<<<(NPACK * IDIM + 255) / 256, 256>>>(W_ih);
    {
        size_t n = (size_t)BATCH * TLEN * IDIM;
        convert_x_kernel<<<(unsigned)((n + 255) / 256), 256>>>(x);
    }
    init_h_kernel<<<(BATCH * HDIM + 255) / 256, 256>>>();

    xg_gemm_kernel<<<dim3(16, (BATCH * TLEN) / MTILE), NTH>>>();

    gru_scan_kernel<<<dim3(16, 8), NTH, DSMEM>>>(b_ih, b_hh);

    final_linear_kernel<<<(BATCH * 32 + 255) / 256, 256>>>(W_lin, b_lin, out);
}